// round 16
// baseline (speedup 1.0000x reference)
#include <cuda_runtime.h>
#include <cuda_fp16.h>
#include <cstdint>
#include <math.h>

// ---------------- problem constants ----------------
namespace cfg {
constexpr int Bb    = 2;
constexpr int Ss    = 4096;
constexpr int DM    = 3584;
constexpr int Hh    = 112;
constexpr int DH    = 64;
constexpr int CHUNK = 256;
constexpr int INNER = Hh * DH;          // 7168
constexpr int M1    = Bb * Ss;          // 8192
constexpr int N1    = 2 * INNER;        // 14336
constexpr int K1    = DM;               // 3584
constexpr int N2    = DM;               // 3584
constexpr int K2    = INNER;            // 7168
constexpr int NCH   = Ss / CHUNK;       // 16
}

// ---------------- scratch (no cudaMalloc allowed) ----------------
__device__ __half g_xzh[(size_t)cfg::M1 * cfg::N1];  // GEMM1 out (fp16)
__device__ __half g_yh [(size_t)cfg::M1 * cfg::K2];  // scan out (fp16)
__device__ __half g_a1h[(size_t)cfg::M1 * cfg::K1];  // hs    (fp16)
__device__ __half g_w1h[(size_t)cfg::N1 * cfg::K1];  // W_in  (fp16)
__device__ __half g_w2h[(size_t)cfg::N2 * cfg::K2];  // W_out (fp16)
__device__ __half g_sigtabh[16384];                  // sigmoid LUT (fp16, bit-indexed)
__device__ float  g_ahtab[cfg::Hh];                  // exp(-|A_log|)

// ---------------- helpers ----------------
__device__ __forceinline__ uint32_t smem_u32(const void* p) {
    uint32_t a;
    asm("{ .reg .u64 t; cvta.to.shared.u64 t, %1; cvt.u32.u64 %0, t; }" : "=r"(a) : "l"(p));
    return a;
}
__device__ __forceinline__ void cp_async16(uint32_t smem_addr, const void* gmem) {
    asm volatile("cp.async.cg.shared.global [%0], [%1], 16;" :: "r"(smem_addr), "l"(gmem) : "memory");
}
__device__ __forceinline__ void ldsm_x4(uint32_t& r0, uint32_t& r1, uint32_t& r2, uint32_t& r3,
                                        uint32_t addr) {
    asm volatile("ldmatrix.sync.aligned.m8n8.x4.shared.b16 {%0,%1,%2,%3}, [%4];"
                 : "=r"(r0), "=r"(r1), "=r"(r2), "=r"(r3) : "r"(addr));
}
__device__ __forceinline__ void ldsm_x2(uint32_t& r0, uint32_t& r1, uint32_t addr) {
    asm volatile("ldmatrix.sync.aligned.m8n8.x2.shared.b16 {%0,%1}, [%2];"
                 : "=r"(r0), "=r"(r1) : "r"(addr));
}
__device__ __forceinline__ void mma_f16_16816(float d[4], const uint32_t a[4], const uint32_t b[2]) {
    asm volatile(
        "mma.sync.aligned.m16n8k16.row.col.f32.f16.f16.f32 "
        "{%0,%1,%2,%3}, {%4,%5,%6,%7}, {%8,%9}, {%0,%1,%2,%3};"
        : "+f"(d[0]), "+f"(d[1]), "+f"(d[2]), "+f"(d[3])
        : "r"(a[0]), "r"(a[1]), "r"(a[2]), "r"(a[3]),
          "r"(b[0]), "r"(b[1]));
}
__device__ __forceinline__ uint32_t h2_bits(__half2 h) {
    union { __half2 h; uint32_t u; } cvt;
    cvt.h = h;
    return cvt.u;
}

// ---------------- fp16 GEMM: C[M,N] = A[M,K] * B[N,K]^T ----------------
// BM=128, BN=NT*16 (NT=8 or 7), BK=64, 3-stage cp.async, 128 threads
// (4 warps 2x2, warp tile 64 x NT*8), 2 CTAs/SM. NT=7 cuts GEMM2's wave
// quantization (2048 tiles / 296 slots = 6.92 waves vs 6.05->7).
#define GBM 128
#define GBK 64
#define GSTG 3

template <int NT>
struct GP {
    static constexpr int BN        = NT * 16;
    static constexpr int STG       = 16384 + NT * 2048;   // A 16KB + B NT*2KB
    static constexpr int SMEM      = GSTG * STG;
};

template <typename OutT, int NT>
__global__ __launch_bounds__(128, 2)
void gemm_f16(const __half* __restrict__ A, const __half* __restrict__ B,
              OutT* __restrict__ C, int M, int N, int K)
{
    constexpr int BN  = GP<NT>::BN;
    constexpr int STG = GP<NT>::STG;
    constexpr int NPAIR = NT / 2;
    constexpr bool TAIL = (NT & 1) != 0;

    extern __shared__ char smem[];
    const uint32_t smem_b = smem_u32(smem);

    const int tid  = threadIdx.x;
    const int lane = tid & 31;
    const int wid  = tid >> 5;          // 0..3
    const int gq   = lane >> 2;
    const int tg   = lane & 3;
    const int m_w  = (wid >> 1) * 64;
    const int n_w  = (wid & 1) * (NT * 8);

    const int nTm = M / GBM, nTn = N / BN;
    constexpr int GROUP = 8;
    const int npg     = GROUP * nTn;
    const int gidx    = blockIdx.x / npg;
    const int first_m = gidx * GROUP;
    const int gsz     = min(nTm - first_m, GROUP);
    const int inG     = blockIdx.x % npg;
    const int m0 = (first_m + (inG % gsz)) * GBM;
    const int n0 = (inG / gsz) * BN;

    const __half* Abase = A + (size_t)m0 * K;
    const __half* Bbase = B + (size_t)n0 * K;

    auto load_stage = [&](int slot, int st) {
        const uint32_t sa = smem_b + slot * STG;
        const uint32_t sb = sa + 16384;
        const __half* Ag = Abase + st * GBK;
        const __half* Bg = Bbase + st * GBK;
        #pragma unroll
        for (int p = 0; p < 8; p++) {           // A: 1024 granules
            const int idx = tid + p * 128;
            const int row = idx >> 3;
            const int g   = idx & 7;
            const int gs  = g ^ (row & 7);
            cp_async16(sa + (uint32_t)(row * 128 + gs * 16), Ag + (size_t)row * K + g * 8);
        }
        #pragma unroll
        for (int p = 0; p < NT; p++) {          // B: NT*128 granules (rows 0..BN-1)
            const int idx = tid + p * 128;
            const int row = idx >> 3;
            const int g   = idx & 7;
            const int gs  = g ^ (row & 7);
            cp_async16(sb + (uint32_t)(row * 128 + gs * 16), Bg + (size_t)row * K + g * 8);
        }
        asm volatile("cp.async.commit_group;" ::: "memory");
    };

    #pragma unroll
    for (int s = 0; s < GSTG - 1; s++) load_stage(s, s);

    float acc[4][NT][4];
    #pragma unroll
    for (int i = 0; i < 4; i++)
        #pragma unroll
        for (int j = 0; j < NT; j++)
            #pragma unroll
            for (int r = 0; r < 4; r++) acc[i][j][r] = 0.f;

    // ---- per-lane ldmatrix row geometry ----
    const int a_r     = ((lane >> 3) & 1) * 8 + (lane & 7);
    const int a_kpart = lane >> 4;
    const int b_r     = (lane >> 4) * 8 + (lane & 7);
    const int b_kpart = (lane >> 3) & 1;

    int aRow[4], aR7[4];
    #pragma unroll
    for (int mt = 0; mt < 4; mt++) {
        aRow[mt] = (m_w + mt * 16 + a_r) * 128;
        aR7[mt]  = (m_w + mt * 16 + a_r) & 7;
    }
    int bRow[NPAIR], bR7[NPAIR];
    #pragma unroll
    for (int ntp = 0; ntp < NPAIR; ntp++) {
        bRow[ntp] = (n_w + ntp * 16 + b_r) * 128;
        bR7[ntp]  = (n_w + ntp * 16 + b_r) & 7;
    }
    // tail n-tile (NT odd): ldsm.x2, lanes 0-15 address two k-halves of 8 rows
    int bRowT = 0, bR7T = 0, b_kpartT = 0;
    if constexpr (TAIL) {
        const int rT = n_w + (NT - 1) * 8 + (lane & 7);
        bRowT = rT * 128;
        bR7T  = rT & 7;
        b_kpartT = (lane >> 3) & 1;
    }

    uint32_t af[2][4][4];
    uint32_t bf[2][NT][2];

    auto ldfrag = [&](int buf, uint32_t sa, uint32_t sb, int step) {
        const int gbase = step * 2;
        #pragma unroll
        for (int mt = 0; mt < 4; mt++) {
            const uint32_t addr = sa + aRow[mt] + (((gbase + a_kpart) ^ aR7[mt]) << 4);
            ldsm_x4(af[buf][mt][0], af[buf][mt][1], af[buf][mt][2], af[buf][mt][3], addr);
        }
        #pragma unroll
        for (int ntp = 0; ntp < NPAIR; ntp++) {
            const uint32_t addr = sb + bRow[ntp] + (((gbase + b_kpart) ^ bR7[ntp]) << 4);
            ldsm_x4(bf[buf][2*ntp][0], bf[buf][2*ntp][1],
                    bf[buf][2*ntp+1][0], bf[buf][2*ntp+1][1], addr);
        }
        if constexpr (TAIL) {
            const uint32_t addr = sb + bRowT + (((gbase + b_kpartT) ^ bR7T) << 4);
            ldsm_x2(bf[buf][NT-1][0], bf[buf][NT-1][1], addr);
        }
    };

    const int nst = K / GBK;
    for (int st = 0; st < nst; ++st) {
        asm volatile("cp.async.wait_group 1;" ::: "memory");
        __syncthreads();

        const int slot = st % GSTG;
        if (st + GSTG - 1 < nst) load_stage((st + GSTG - 1) % GSTG, st + GSTG - 1);
        else asm volatile("cp.async.commit_group;" ::: "memory");

        const uint32_t sa = smem_b + slot * STG;
        const uint32_t sb = sa + 16384;

        ldfrag(0, sa, sb, 0);
        #pragma unroll
        for (int k16 = 0; k16 < 4; ++k16) {
            if (k16 < 3) ldfrag((k16 + 1) & 1, sa, sb, k16 + 1);
            const int buf = k16 & 1;
            #pragma unroll
            for (int mt = 0; mt < 4; mt++)
                #pragma unroll
                for (int nt = 0; nt < NT; nt++)
                    mma_f16_16816(acc[mt][nt], af[buf][mt], bf[buf][nt]);
        }
    }

    // ---- epilogue: stage through padded smem, then coalesced STG.128 ----
    __syncthreads();

    if constexpr (sizeof(OutT) == 2) {
        constexpr int ROWB = BN * 2;          // bytes per staged row
        constexpr int RB   = ROWB + 16;
        constexpr int GPR  = ROWB / 16;       // granules per row
        #pragma unroll
        for (int mt = 0; mt < 4; mt++) {
            const int r0 = m_w + mt * 16 + gq;
            #pragma unroll
            for (int nt = 0; nt < NT; nt++) {
                const int c = n_w + nt * 8 + tg * 2;
                *(__half2*)(smem + r0 * RB + c * 2)       = __floats2half2_rn(acc[mt][nt][0], acc[mt][nt][1]);
                *(__half2*)(smem + (r0 + 8) * RB + c * 2) = __floats2half2_rn(acc[mt][nt][2], acc[mt][nt][3]);
            }
        }
        __syncthreads();
        #pragma unroll
        for (int pass = 0; pass < GPR * 128 / 128; pass++) {
            const int idx = pass * 128 + tid;
            const int row = idx / GPR;
            const int g   = idx % GPR;
            const uint4 v = *(const uint4*)(smem + row * RB + g * 16);
            *(uint4*)&C[(size_t)(m0 + row) * N + n0 + g * 8] = v;
        }
    } else {
        constexpr int ROWB = BN * 4;
        constexpr int RB   = ROWB + 32;
        constexpr int GPR  = ROWB / 16;
        #pragma unroll
        for (int mt = 0; mt < 4; mt++) {
            const int r0 = m_w + mt * 16 + gq;
            #pragma unroll
            for (int nt = 0; nt < NT; nt++) {
                const int c = n_w + nt * 8 + tg * 2;
                *(float2*)(smem + r0 * RB + c * 4)       = make_float2(acc[mt][nt][0], acc[mt][nt][1]);
                *(float2*)(smem + (r0 + 8) * RB + c * 4) = make_float2(acc[mt][nt][2], acc[mt][nt][3]);
            }
        }
        __syncthreads();
        #pragma unroll
        for (int pass = 0; pass < GPR; pass++) {
            const int idx = pass * 128 + tid;
            const int row = idx / GPR;
            const int g   = idx % GPR;
            const uint4 v = *(const uint4*)(smem + row * RB + g * 16);
            *(uint4*)&C[(size_t)(m0 + row) * N + n0 + g * 4] = v;
        }
    }
}

// ---------------- fp32 -> fp16 conversion ----------------
__global__ __launch_bounds__(256)
void tohalf_kernel(const float* __restrict__ in, __half* __restrict__ out, int n8)
{
    const int i = blockIdx.x * blockDim.x + threadIdx.x;
    if (i >= n8) return;
    const float4 r0 = ((const float4*)in)[2 * i];
    const float4 r1 = ((const float4*)in)[2 * i + 1];
    uint4 u;
    u.x = h2_bits(__floats2half2_rn(r0.x, r0.y));
    u.y = h2_bits(__floats2half2_rn(r0.z, r0.w));
    u.z = h2_bits(__floats2half2_rn(r1.x, r1.y));
    u.w = h2_bits(__floats2half2_rn(r1.z, r1.w));
    ((uint4*)out)[i] = u;
}

// ---------------- LUT init kernels ----------------
__global__ void sigtab_init(__half* __restrict__ tab)
{
    const int j = blockIdx.x * 256 + threadIdx.x;   // 0..16383
    const unsigned short bits = (unsigned short)(j << 2);
    const float z = __half2float(__ushort_as_half(bits));
    tab[j] = __float2half_rn(1.f / (1.f + expf(-z)));
}
__global__ void ahtab_init(const float* __restrict__ A_log, float* __restrict__ tab)
{
    const int h = threadIdx.x;
    if (h < cfg::Hh) tab[h] = expf(-fabsf(A_log[h]));
}

// ---------------- scan + gate v4 (unchanged): fp16 LUT, 2 cols/thread ----------------
#define SCAN_BLOCKS 448
#define SCAN_THREADS 512

__global__ __launch_bounds__(SCAN_THREADS, 4)
void scan_gate_v4(const float* __restrict__ ahtab,
                  const __half* __restrict__ sigtab,
                  const __half* __restrict__ xz,
                  __half* __restrict__ y)
{
    using namespace cfg;
    extern __shared__ __half stab[];
    {
        const float4* src = (const float4*)sigtab;
        float4* dst = (float4*)stab;
        for (int i = threadIdx.x; i < 2048; i += SCAN_THREADS) dst[i] = src[i];
    }
    __syncthreads();
    const char* tabc = (const char*)stab;

    constexpr int OCTS = INNER / 8;
    #pragma unroll
    for (int pass = 0; pass < 2; pass++) {
        const int col = pass * (SCAN_BLOCKS * SCAN_THREADS) + blockIdx.x * SCAN_THREADS + threadIdx.x;
        const int o  = col % OCTS;
        const int bt = col / OCTS;
        const int t  = bt % CHUNK;
        const int b  = bt / CHUNK;
        const int inner = o * 8;

        const float Ah = ahtab[inner >> 6];
        float h[8];
        #pragma unroll
        for (int i = 0; i < 8; i++) h[i] = 0.f;

        const __half* xp = xz + ((size_t)b * Ss + t) * (size_t)N1 + inner;
        __half*       yp = y  + ((size_t)b * Ss + t) * (size_t)INNER + inner;
        const size_t xstep = (size_t)CHUNK * N1;
        const size_t ystep = (size_t)CHUNK * INNER;

        #pragma unroll
        for (int c = 0; c < NCH; c++) {
            const uint4 xu = *(const uint4*)xp;
            const uint4 zu = *(const uint4*)(xp + INNER);

            const float2 x01 = __half22float2(*(const __half2*)&xu.x);
            const float2 x23 = __half22float2(*(const __half2*)&xu.y);
            const float2 x45 = __half22float2(*(const __half2*)&xu.z);
            const float2 x67 = __half22float2(*(const __half2*)&xu.w);
            h[0] = h[0] * Ah + 0.1f * x01.x;  h[1] = h[1] * Ah + 0.1f * x01.y;
            h[2] = h[2] * Ah + 0.1f * x23.x;  h[3] = h[3] * Ah + 0.1f * x23.y;
            h[4] = h[4] * Ah + 0.1f * x45.x;  h[5] = h[5] * Ah + 0.1f * x45.y;
            h[6] = h[6] * Ah + 0.1f * x67.x;  h[7] = h[7] * Ah + 0.1f * x67.y;

            const uint32_t za = zu.x + 0x00020002u;
            const uint32_t zb = zu.y + 0x00020002u;
            const uint32_t zc = zu.z + 0x00020002u;
            const uint32_t zd = zu.w + 0x00020002u;
            const float s0 = __half2float(*(const __half*)(tabc + ((za & 0xFFFCu) >> 1)));
            const float s1 = __half2float(*(const __half*)(tabc + (((za >> 16) & 0xFFFCu) >> 1)));
            const float s2 = __half2float(*(const __half*)(tabc + ((zb & 0xFFFCu) >> 1)));
            const float s3 = __half2float(*(const __half*)(tabc + (((zb >> 16) & 0xFFFCu) >> 1)));
            const float s4 = __half2float(*(const __half*)(tabc + ((zc & 0xFFFCu) >> 1)));
            const float s5 = __half2float(*(const __half*)(tabc + (((zc >> 16) & 0xFFFCu) >> 1)));
            const float s6 = __half2float(*(const __half*)(tabc + ((zd & 0xFFFCu) >> 1)));
            const float s7 = __half2float(*(const __half*)(tabc + (((zd >> 16) & 0xFFFCu) >> 1)));

            uint4 yo;
            yo.x = h2_bits(__floats2half2_rn(h[0] * s0, h[1] * s1));
            yo.y = h2_bits(__floats2half2_rn(h[2] * s2, h[3] * s3));
            yo.z = h2_bits(__floats2half2_rn(h[4] * s4, h[5] * s5));
            yo.w = h2_bits(__floats2half2_rn(h[6] * s6, h[7] * s7));
            *(uint4*)yp = yo;

            xp += xstep;
            yp += ystep;
        }
    }
}

// ---------------- launch ----------------
extern "C" void kernel_launch(void* const* d_in, const int* in_sizes, int n_in,
                              void* d_out, int out_size)
{
    using namespace cfg;
    const float* hs    = (const float*)d_in[0];
    const float* W_in  = (const float*)d_in[1];
    const float* W_out = (const float*)d_in[2];
    const float* A_log = (const float*)d_in[3];
    float* out = (float*)d_out;

    __half *xzh, *yh, *a1h, *w1h, *w2h, *sigtabh;
    float *ahtab;
    cudaGetSymbolAddress((void**)&xzh, g_xzh);
    cudaGetSymbolAddress((void**)&yh,  g_yh);
    cudaGetSymbolAddress((void**)&a1h, g_a1h);
    cudaGetSymbolAddress((void**)&w1h, g_w1h);
    cudaGetSymbolAddress((void**)&w2h, g_w2h);
    cudaGetSymbolAddress((void**)&sigtabh, g_sigtabh);
    cudaGetSymbolAddress((void**)&ahtab,   g_ahtab);

    cudaFuncSetAttribute((const void*)gemm_f16<__half, 8>, cudaFuncAttributeMaxDynamicSharedMemorySize, GP<8>::SMEM);
    cudaFuncSetAttribute((const void*)gemm_f16<float, 7>,  cudaFuncAttributeMaxDynamicSharedMemorySize, GP<7>::SMEM);
    cudaFuncSetAttribute(scan_gate_v4, cudaFuncAttributeMaxDynamicSharedMemorySize, 32768);

    // LUTs
    sigtab_init<<<64, 256>>>(sigtabh);
    ahtab_init<<<1, 128>>>(A_log, ahtab);

    // convert GEMM operands to fp16
    {
        int n8;
        n8 = (M1 * K1) / 8; tohalf_kernel<<<(n8 + 255) / 256, 256>>>(hs,    a1h, n8);
        n8 = (N1 * K1) / 8; tohalf_kernel<<<(n8 + 255) / 256, 256>>>(W_in,  w1h, n8);
        n8 = (N2 * K2) / 8; tohalf_kernel<<<(n8 + 255) / 256, 256>>>(W_out, w2h, n8);
    }

    // GEMM1: xz = hs @ W_in^T   (M=8192, N=14336, K=3584) -> fp16, BN=128
    gemm_f16<__half, 8><<<(M1 / GBM) * (N1 / GP<8>::BN), 128, GP<8>::SMEM>>>(a1h, w1h, xzh, M1, N1, K1);

    // scan + gate -> fp16 y
    scan_gate_v4<<<SCAN_BLOCKS, SCAN_THREADS, 32768>>>(ahtab, sigtabh, xzh, yh);

    // GEMM2: out = y @ W_out^T  (M=8192, N=3584, K=7168) -> fp32, BN=112 (anti wave-quant)
    gemm_f16<float, 7><<<(M1 / GBM) * (N2 / GP<7>::BN), 128, GP<7>::SMEM>>>(yh, w2h, out, M1, N2, K2);
}

// round 17
// speedup vs baseline: 1.0058x; 1.0058x over previous
#include <cuda_runtime.h>
#include <cuda_fp16.h>
#include <cstdint>
#include <math.h>

// ---------------- problem constants ----------------
namespace cfg {
constexpr int Bb    = 2;
constexpr int Ss    = 4096;
constexpr int DM    = 3584;
constexpr int Hh    = 112;
constexpr int DH    = 64;
constexpr int CHUNK = 256;
constexpr int INNER = Hh * DH;          // 7168
constexpr int M1    = Bb * Ss;          // 8192
constexpr int N1    = 2 * INNER;        // 14336
constexpr int K1    = DM;               // 3584
constexpr int N2    = DM;               // 3584
constexpr int K2    = INNER;            // 7168
constexpr int NCH   = Ss / CHUNK;       // 16
}

// ---------------- scratch (no cudaMalloc allowed) ----------------
__device__ __half g_xzh[(size_t)cfg::M1 * cfg::N1];  // GEMM1 out (fp16)
__device__ __half g_yh [(size_t)cfg::M1 * cfg::K2];  // scan out (fp16)
__device__ __half g_a1h[(size_t)cfg::M1 * cfg::K1];  // hs    (fp16)
__device__ __half g_w1h[(size_t)cfg::N1 * cfg::K1];  // W_in  (fp16)
__device__ __half g_w2h[(size_t)cfg::N2 * cfg::K2];  // W_out (fp16)
__device__ __half g_sigtabh[16384];                  // sigmoid LUT (fp16, bit-indexed)
__device__ float  g_ahtab[cfg::Hh];                  // exp(-|A_log|)

// ---------------- helpers ----------------
__device__ __forceinline__ uint32_t smem_u32(const void* p) {
    uint32_t a;
    asm("{ .reg .u64 t; cvta.to.shared.u64 t, %1; cvt.u32.u64 %0, t; }" : "=r"(a) : "l"(p));
    return a;
}
__device__ __forceinline__ void cp_async16(uint32_t smem_addr, const void* gmem) {
    asm volatile("cp.async.cg.shared.global [%0], [%1], 16;" :: "r"(smem_addr), "l"(gmem) : "memory");
}
__device__ __forceinline__ void ldsm_x4(uint32_t& r0, uint32_t& r1, uint32_t& r2, uint32_t& r3,
                                        uint32_t addr) {
    asm volatile("ldmatrix.sync.aligned.m8n8.x4.shared.b16 {%0,%1,%2,%3}, [%4];"
                 : "=r"(r0), "=r"(r1), "=r"(r2), "=r"(r3) : "r"(addr));
}
__device__ __forceinline__ void mma_f16_16816(float d[4], const uint32_t a[4], const uint32_t b[2]) {
    asm volatile(
        "mma.sync.aligned.m16n8k16.row.col.f32.f16.f16.f32 "
        "{%0,%1,%2,%3}, {%4,%5,%6,%7}, {%8,%9}, {%0,%1,%2,%3};"
        : "+f"(d[0]), "+f"(d[1]), "+f"(d[2]), "+f"(d[3])
        : "r"(a[0]), "r"(a[1]), "r"(a[2]), "r"(a[3]),
          "r"(b[0]), "r"(b[1]));
}
__device__ __forceinline__ uint32_t h2_bits(__half2 h) {
    union { __half2 h; uint32_t u; } cvt;
    cvt.h = h;
    return cvt.u;
}

// ---------------- fp16 GEMM (R14-proven): C[M,N] = A[M,K] * B[N,K]^T ----------------
// BM=128, BN=128, BK=64 (128B rows, XOR-16B swizzle), 3-stage cp.async (96 KB),
// 128 threads (4 warps 2x2, warp tile 64x64), 2 CTAs/SM, ldmatrix.x4 fragments,
// register double-buffered k16 steps, smem-staged coalesced epilogue.
#define GBM 128
#define GBN 128
#define GBK 64
#define STG_BYTES 32768
#define GSTG 3
#define GSMEM_BYTES (GSTG * STG_BYTES)       // 96 KB (also covers epilogue staging)

template <typename OutT>
__global__ __launch_bounds__(128, 2)
void gemm_f16(const __half* __restrict__ A, const __half* __restrict__ B,
              OutT* __restrict__ C, int M, int N, int K)
{
    extern __shared__ char smem[];
    const uint32_t smem_b = smem_u32(smem);

    const int tid  = threadIdx.x;
    const int lane = tid & 31;
    const int wid  = tid >> 5;          // 0..3
    const int gq   = lane >> 2;
    const int tg   = lane & 3;
    const int m_w  = (wid >> 1) * 64;
    const int n_w  = (wid & 1) * 64;

    const int nTm = M / GBM, nTn = N / GBN;
    constexpr int GROUP = 8;
    const int npg     = GROUP * nTn;
    const int gidx    = blockIdx.x / npg;
    const int first_m = gidx * GROUP;
    const int gsz     = min(nTm - first_m, GROUP);
    const int inG     = blockIdx.x % npg;
    const int m0 = (first_m + (inG % gsz)) * GBM;
    const int n0 = (inG / gsz) * GBN;

    const __half* Abase = A + (size_t)m0 * K;
    const __half* Bbase = B + (size_t)n0 * K;

    auto load_stage = [&](int slot, int st) {
        const uint32_t sa = smem_b + slot * STG_BYTES;
        const uint32_t sb = sa + 16384;
        const __half* Ag = Abase + st * GBK;
        const __half* Bg = Bbase + st * GBK;
        #pragma unroll
        for (int p = 0; p < 8; p++) {
            const int idx = tid + p * 128;
            const int row = idx >> 3;
            const int g   = idx & 7;
            const int gs  = g ^ (row & 7);
            const uint32_t doff = (uint32_t)(row * 128 + gs * 16);
            cp_async16(sa + doff, Ag + (size_t)row * K + g * 8);
            cp_async16(sb + doff, Bg + (size_t)row * K + g * 8);
        }
        asm volatile("cp.async.commit_group;" ::: "memory");
    };

    #pragma unroll
    for (int s = 0; s < GSTG - 1; s++) load_stage(s, s);

    float acc[4][8][4];
    #pragma unroll
    for (int i = 0; i < 4; i++)
        #pragma unroll
        for (int j = 0; j < 8; j++)
            #pragma unroll
            for (int r = 0; r < 4; r++) acc[i][j][r] = 0.f;

    const int a_r     = ((lane >> 3) & 1) * 8 + (lane & 7);
    const int a_kpart = lane >> 4;
    const int b_r     = (lane >> 4) * 8 + (lane & 7);
    const int b_kpart = (lane >> 3) & 1;

    int aRow[4], aR7[4];
    #pragma unroll
    for (int mt = 0; mt < 4; mt++) {
        aRow[mt] = (m_w + mt * 16 + a_r) * 128;
        aR7[mt]  = (m_w + mt * 16 + a_r) & 7;
    }
    int bRow[4], bR7[4];
    #pragma unroll
    for (int ntp = 0; ntp < 4; ntp++) {
        bRow[ntp] = (n_w + ntp * 16 + b_r) * 128;
        bR7[ntp]  = (n_w + ntp * 16 + b_r) & 7;
    }

    uint32_t af[2][4][4];
    uint32_t bf[2][8][2];

    auto ldfrag = [&](int buf, uint32_t sa, uint32_t sb, int step) {
        const int gbase = step * 2;
        #pragma unroll
        for (int mt = 0; mt < 4; mt++) {
            const uint32_t addr = sa + aRow[mt] + (((gbase + a_kpart) ^ aR7[mt]) << 4);
            ldsm_x4(af[buf][mt][0], af[buf][mt][1], af[buf][mt][2], af[buf][mt][3], addr);
        }
        #pragma unroll
        for (int ntp = 0; ntp < 4; ntp++) {
            const uint32_t addr = sb + bRow[ntp] + (((gbase + b_kpart) ^ bR7[ntp]) << 4);
            ldsm_x4(bf[buf][2*ntp][0], bf[buf][2*ntp][1],
                    bf[buf][2*ntp+1][0], bf[buf][2*ntp+1][1], addr);
        }
    };

    const int nst = K / GBK;
    for (int st = 0; st < nst; ++st) {
        asm volatile("cp.async.wait_group 1;" ::: "memory");
        __syncthreads();

        const int slot = st % GSTG;
        if (st + GSTG - 1 < nst) load_stage((st + GSTG - 1) % GSTG, st + GSTG - 1);
        else asm volatile("cp.async.commit_group;" ::: "memory");

        const uint32_t sa = smem_b + slot * STG_BYTES;
        const uint32_t sb = sa + 16384;

        ldfrag(0, sa, sb, 0);
        #pragma unroll
        for (int k16 = 0; k16 < 4; ++k16) {
            if (k16 < 3) ldfrag((k16 + 1) & 1, sa, sb, k16 + 1);
            const int buf = k16 & 1;
            #pragma unroll
            for (int mt = 0; mt < 4; mt++)
                #pragma unroll
                for (int nt = 0; nt < 8; nt++)
                    mma_f16_16816(acc[mt][nt], af[buf][mt], bf[buf][nt]);
        }
    }

    // ---- epilogue: stage through padded smem, then coalesced STG.128 ----
    __syncthreads();

    if constexpr (sizeof(OutT) == 2) {
        constexpr int RB = 272;
        #pragma unroll
        for (int mt = 0; mt < 4; mt++) {
            const int r0 = m_w + mt * 16 + gq;
            #pragma unroll
            for (int nt = 0; nt < 8; nt++) {
                const int c = n_w + nt * 8 + tg * 2;
                *(__half2*)(smem + r0 * RB + c * 2)       = __floats2half2_rn(acc[mt][nt][0], acc[mt][nt][1]);
                *(__half2*)(smem + (r0 + 8) * RB + c * 2) = __floats2half2_rn(acc[mt][nt][2], acc[mt][nt][3]);
            }
        }
        __syncthreads();
        #pragma unroll
        for (int pass = 0; pass < 16; pass++) {
            const int idx = pass * 128 + tid;
            const int row = idx >> 4;
            const int g   = idx & 15;
            const uint4 v = *(const uint4*)(smem + row * RB + g * 16);
            *(uint4*)&C[(size_t)(m0 + row) * N + n0 + g * 8] = v;
        }
    } else {
        constexpr int RB = 544;
        #pragma unroll
        for (int mt = 0; mt < 4; mt++) {
            const int r0 = m_w + mt * 16 + gq;
            #pragma unroll
            for (int nt = 0; nt < 8; nt++) {
                const int c = n_w + nt * 8 + tg * 2;
                *(float2*)(smem + r0 * RB + c * 4)       = make_float2(acc[mt][nt][0], acc[mt][nt][1]);
                *(float2*)(smem + (r0 + 8) * RB + c * 4) = make_float2(acc[mt][nt][2], acc[mt][nt][3]);
            }
        }
        __syncthreads();
        #pragma unroll
        for (int pass = 0; pass < 32; pass++) {
            const int idx = pass * 128 + tid;
            const int row = idx >> 5;
            const int g   = idx & 31;
            const uint4 v = *(const uint4*)(smem + row * RB + g * 16);
            *(uint4*)&C[(size_t)(m0 + row) * N + n0 + g * 4] = v;
        }
    }
}

// ---------------- merged fp32 -> fp16 conversion (3 arrays, one launch) ----------------
__global__ __launch_bounds__(256)
void tohalf3_kernel(const float* __restrict__ in0, __half* __restrict__ out0, int n80,
                    const float* __restrict__ in1, __half* __restrict__ out1, int n81,
                    const float* __restrict__ in2, __half* __restrict__ out2, int n82)
{
    int i = blockIdx.x * blockDim.x + threadIdx.x;
    const float* in;
    __half* out;
    if (i < n80)            { in = in0; out = out0; }
    else if (i < n80 + n81) { i -= n80; in = in1; out = out1; }
    else                    { i -= n80 + n81; if (i >= n82) return; in = in2; out = out2; }

    const float4 r0 = ((const float4*)in)[2 * i];
    const float4 r1 = ((const float4*)in)[2 * i + 1];
    uint4 u;
    u.x = h2_bits(__floats2half2_rn(r0.x, r0.y));
    u.y = h2_bits(__floats2half2_rn(r0.z, r0.w));
    u.z = h2_bits(__floats2half2_rn(r1.x, r1.y));
    u.w = h2_bits(__floats2half2_rn(r1.z, r1.w));
    ((uint4*)out)[i] = u;
}

// ---------------- merged LUT init (sigmoid table + Ah table) ----------------
__global__ void luts_init(const float* __restrict__ A_log,
                          __half* __restrict__ sigtab, float* __restrict__ ahtab)
{
    const int j = blockIdx.x * 256 + threadIdx.x;   // 0..16383
    const unsigned short bits = (unsigned short)(j << 2);
    const float z = __half2float(__ushort_as_half(bits));
    sigtab[j] = __float2half_rn(1.f / (1.f + expf(-z)));
    if (j < cfg::Hh) ahtab[j] = expf(-fabsf(A_log[j]));
}

// ---------------- scan + gate v4: fp16 LUT (32 KB), exact 2 columns/thread ----------------
#define SCAN_BLOCKS 448
#define SCAN_THREADS 512

__global__ __launch_bounds__(SCAN_THREADS, 4)
void scan_gate_v4(const float* __restrict__ ahtab,
                  const __half* __restrict__ sigtab,
                  const __half* __restrict__ xz,
                  __half* __restrict__ y)
{
    using namespace cfg;
    extern __shared__ __half stab[];   // 32 KB sigmoid table (fp16)
    {
        const float4* src = (const float4*)sigtab;
        float4* dst = (float4*)stab;
        for (int i = threadIdx.x; i < 2048; i += SCAN_THREADS) dst[i] = src[i];
    }
    __syncthreads();
    const char* tabc = (const char*)stab;

    constexpr int OCTS = INNER / 8;                   // 896 groups of 8 elements
    #pragma unroll
    for (int pass = 0; pass < 2; pass++) {
        const int col = pass * (SCAN_BLOCKS * SCAN_THREADS) + blockIdx.x * SCAN_THREADS + threadIdx.x;
        const int o  = col % OCTS;
        const int bt = col / OCTS;
        const int t  = bt % CHUNK;
        const int b  = bt / CHUNK;
        const int inner = o * 8;

        const float Ah = ahtab[inner >> 6];   // all 8 elems in one head (DH=64)
        float h[8];
        #pragma unroll
        for (int i = 0; i < 8; i++) h[i] = 0.f;

        const __half* xp = xz + ((size_t)b * Ss + t) * (size_t)N1 + inner;
        __half*       yp = y  + ((size_t)b * Ss + t) * (size_t)INNER + inner;
        const size_t xstep = (size_t)CHUNK * N1;
        const size_t ystep = (size_t)CHUNK * INNER;

        #pragma unroll
        for (int c = 0; c < NCH; c++) {
            const uint4 xu = *(const uint4*)xp;
            const uint4 zu = *(const uint4*)(xp + INNER);

            const float2 x01 = __half22float2(*(const __half2*)&xu.x);
            const float2 x23 = __half22float2(*(const __half2*)&xu.y);
            const float2 x45 = __half22float2(*(const __half2*)&xu.z);
            const float2 x67 = __half22float2(*(const __half2*)&xu.w);
            h[0] = h[0] * Ah + 0.1f * x01.x;  h[1] = h[1] * Ah + 0.1f * x01.y;
            h[2] = h[2] * Ah + 0.1f * x23.x;  h[3] = h[3] * Ah + 0.1f * x23.y;
            h[4] = h[4] * Ah + 0.1f * x45.x;  h[5] = h[5] * Ah + 0.1f * x45.y;
            h[6] = h[6] * Ah + 0.1f * x67.x;  h[7] = h[7] * Ah + 0.1f * x67.y;

            const uint32_t za = zu.x + 0x00020002u;
            const uint32_t zb = zu.y + 0x00020002u;
            const uint32_t zc = zu.z + 0x00020002u;
            const uint32_t zd = zu.w + 0x00020002u;
            const float s0 = __half2float(*(const __half*)(tabc + ((za & 0xFFFCu) >> 1)));
            const float s1 = __half2float(*(const __half*)(tabc + (((za >> 16) & 0xFFFCu) >> 1)));
            const float s2 = __half2float(*(const __half*)(tabc + ((zb & 0xFFFCu) >> 1)));
            const float s3 = __half2float(*(const __half*)(tabc + (((zb >> 16) & 0xFFFCu) >> 1)));
            const float s4 = __half2float(*(const __half*)(tabc + ((zc & 0xFFFCu) >> 1)));
            const float s5 = __half2float(*(const __half*)(tabc + (((zc >> 16) & 0xFFFCu) >> 1)));
            const float s6 = __half2float(*(const __half*)(tabc + ((zd & 0xFFFCu) >> 1)));
            const float s7 = __half2float(*(const __half*)(tabc + (((zd >> 16) & 0xFFFCu) >> 1)));

            uint4 yo;
            yo.x = h2_bits(__floats2half2_rn(h[0] * s0, h[1] * s1));
            yo.y = h2_bits(__floats2half2_rn(h[2] * s2, h[3] * s3));
            yo.z = h2_bits(__floats2half2_rn(h[4] * s4, h[5] * s5));
            yo.w = h2_bits(__floats2half2_rn(h[6] * s6, h[7] * s7));
            *(uint4*)yp = yo;

            xp += xstep;
            yp += ystep;
        }
    }
}

// ---------------- launch ----------------
extern "C" void kernel_launch(void* const* d_in, const int* in_sizes, int n_in,
                              void* d_out, int out_size)
{
    using namespace cfg;
    const float* hs    = (const float*)d_in[0];
    const float* W_in  = (const float*)d_in[1];
    const float* W_out = (const float*)d_in[2];
    const float* A_log = (const float*)d_in[3];
    float* out = (float*)d_out;

    __half *xzh, *yh, *a1h, *w1h, *w2h, *sigtabh;
    float *ahtab;
    cudaGetSymbolAddress((void**)&xzh, g_xzh);
    cudaGetSymbolAddress((void**)&yh,  g_yh);
    cudaGetSymbolAddress((void**)&a1h, g_a1h);
    cudaGetSymbolAddress((void**)&w1h, g_w1h);
    cudaGetSymbolAddress((void**)&w2h, g_w2h);
    cudaGetSymbolAddress((void**)&sigtabh, g_sigtabh);
    cudaGetSymbolAddress((void**)&ahtab,   g_ahtab);

    cudaFuncSetAttribute(gemm_f16<__half>, cudaFuncAttributeMaxDynamicSharedMemorySize, GSMEM_BYTES);
    cudaFuncSetAttribute(gemm_f16<float>,  cudaFuncAttributeMaxDynamicSharedMemorySize, GSMEM_BYTES);
    cudaFuncSetAttribute(scan_gate_v4,     cudaFuncAttributeMaxDynamicSharedMemorySize, 32768);

    // LUTs (one launch)
    luts_init<<<64, 256>>>(A_log, sigtabh, ahtab);

    // convert all GEMM operands to fp16 (one launch)
    {
        const int n80 = (M1 * K1) / 8;   // hs
        const int n81 = (N1 * K1) / 8;   // W_in
        const int n82 = (N2 * K2) / 8;   // W_out
        const int tot = n80 + n81 + n82;
        tohalf3_kernel<<<(tot + 255) / 256, 256>>>(hs, a1h, n80, W_in, w1h, n81, W_out, w2h, n82);
    }

    // GEMM1: xz = hs @ W_in^T   (M=8192, N=14336, K=3584) -> fp16
    gemm_f16<__half><<<(M1 / GBM) * (N1 / GBN), 128, GSMEM_BYTES>>>(a1h, w1h, xzh, M1, N1, K1);

    // scan + gate -> fp16 y (single wave, 2 columns/thread exact)
    scan_gate_v4<<<SCAN_BLOCKS, SCAN_THREADS, 32768>>>(ahtab, sigtabh, xzh, yh);

    // GEMM2: out = y @ W_out^T  (M=8192, N=3584, K=7168) -> fp32
    gemm_f16<float><<<(M1 / GBM) * (N2 / GBN), 128, GSMEM_BYTES>>>(yh, w2h, out, M1, N2, K2);
}